// round 1
// baseline (speedup 1.0000x reference)
#include <cuda_runtime.h>
#include <cstdint>

#define D_IN  1024
#define D_OUT 1024
#define MAX_N 16384

// ---------------- scratch (device globals; no allocation allowed) ----------
__device__ unsigned g_absmax[2];                 // [0]=x, [1]=w  (abs-max as uint bits)
__device__ int8_t   g_qx[(size_t)MAX_N * D_IN];  // quantized activations
__device__ int8_t   g_qw[(size_t)D_OUT * D_IN];  // quantized weights

// ---------------- kernel 0: reset absmax (graph replays need this) ---------
__global__ void init_kernel() {
    g_absmax[0] = 0u;
    g_absmax[1] = 0u;
}

// ---------------- kernel 1: abs-max reduction ------------------------------
__global__ void absmax_kernel(const float* __restrict__ in, int n4, int which) {
    const float4* p = (const float4*)in;
    unsigned m = 0u;
    for (int i = blockIdx.x * blockDim.x + threadIdx.x; i < n4; i += gridDim.x * blockDim.x) {
        float4 v = p[i];
        m = max(m, __float_as_uint(fabsf(v.x)));
        m = max(m, __float_as_uint(fabsf(v.y)));
        m = max(m, __float_as_uint(fabsf(v.z)));
        m = max(m, __float_as_uint(fabsf(v.w)));
    }
    m = __reduce_max_sync(0xffffffffu, m);
    __shared__ unsigned smax[8];
    int warp = threadIdx.x >> 5, lane = threadIdx.x & 31;
    if (lane == 0) smax[warp] = m;
    __syncthreads();
    if (warp == 0) {
        m = (lane < (blockDim.x >> 5)) ? smax[lane] : 0u;
        m = __reduce_max_sync(0xffffffffu, m);
        if (lane == 0) atomicMax(&g_absmax[which], m);
    }
}

// ---------------- kernel 2: quantize (round-half-even, clamp ±127) --------
__global__ void quant_kernel(const float* __restrict__ in, int8_t* __restrict__ out,
                             int n4, int which) {
    float amax  = __uint_as_float(g_absmax[which]);
    float scale = amax / 127.0f;
    const float4* p = (const float4*)in;
    char4* q = (char4*)out;
    for (int i = blockIdx.x * blockDim.x + threadIdx.x; i < n4; i += gridDim.x * blockDim.x) {
        float4 v = p[i];
        char4 c;
        c.x = (signed char)(int)fminf(fmaxf(rintf(v.x / scale), -127.0f), 127.0f);
        c.y = (signed char)(int)fminf(fmaxf(rintf(v.y / scale), -127.0f), 127.0f);
        c.z = (signed char)(int)fminf(fmaxf(rintf(v.z / scale), -127.0f), 127.0f);
        c.w = (signed char)(int)fminf(fmaxf(rintf(v.w / scale), -127.0f), 127.0f);
        q[i] = c;
    }
}

// ---------------- kernel 3: int8 GEMM + dequant + bias ---------------------
// C[N, D_OUT] = qx[N, D_IN] @ qw[D_OUT, D_IN]^T  (weight row-major == B col-major)
// CTA tile 128x128x64, 8 warps in 4(m) x 2(n), warp tile 32x64,
// mma.sync.aligned.m16n8k32.row.col.s32.s8.s8.s32

#define BM 128
#define BN 128
#define BK 64
#define SSTRIDE 80   // 64B row + 16B pad -> conflict-free LDS.32 fragment reads

__device__ __forceinline__ void mma_s8(int* c, const uint32_t* a, const uint32_t* b) {
    asm volatile(
        "mma.sync.aligned.m16n8k32.row.col.s32.s8.s8.s32 "
        "{%0,%1,%2,%3}, {%4,%5,%6,%7}, {%8,%9}, {%0,%1,%2,%3};"
        : "+r"(c[0]), "+r"(c[1]), "+r"(c[2]), "+r"(c[3])
        : "r"(a[0]), "r"(a[1]), "r"(a[2]), "r"(a[3]), "r"(b[0]), "r"(b[1]));
}

__global__ __launch_bounds__(256, 2)
void gemm_kernel(const float* __restrict__ bias, float* __restrict__ out, int N) {
    __shared__ int8_t sA[BM * SSTRIDE];
    __shared__ int8_t sB[BN * SSTRIDE];

    const int tid  = threadIdx.x;
    const int warp = tid >> 5;
    const int lane = tid & 31;
    const int wm   = warp >> 1;     // 0..3  -> 32 rows each
    const int wn   = warp & 1;      // 0..1  -> 64 cols each
    const int g    = lane >> 2;     // 0..7
    const int tg   = lane & 3;      // 0..3

    const int bm = blockIdx.y * BM;
    const int bn = blockIdx.x * BN;

    const int8_t* gA = g_qx + (size_t)bm * D_IN;
    const int8_t* gB = g_qw + (size_t)bn * D_IN;

    int acc[2][8][4];
#pragma unroll
    for (int mt = 0; mt < 2; mt++)
#pragma unroll
        for (int nt = 0; nt < 8; nt++)
#pragma unroll
            for (int i = 0; i < 4; i++) acc[mt][nt][i] = 0;

    for (int k0 = 0; k0 < D_IN; k0 += BK) {
        // stage tiles: 128 rows x 64B = 512 x 16B chunks each; 256 threads x 2
#pragma unroll
        for (int i = 0; i < 2; i++) {
            int c    = tid + i * 256;
            int row  = c >> 2;
            int col  = (c & 3) * 16;
            *(int4*)&sA[row * SSTRIDE + col] =
                *(const int4*)&gA[(size_t)row * D_IN + k0 + col];
            *(int4*)&sB[row * SSTRIDE + col] =
                *(const int4*)&gB[(size_t)row * D_IN + k0 + col];
        }
        __syncthreads();

#pragma unroll
        for (int ks = 0; ks < 2; ks++) {
            const int kk = ks * 32;
            uint32_t a[2][4], b[8][2];
#pragma unroll
            for (int mt = 0; mt < 2; mt++) {
                int r = wm * 32 + mt * 16 + g;
                a[mt][0] = *(const uint32_t*)&sA[r * SSTRIDE + kk + tg * 4];
                a[mt][1] = *(const uint32_t*)&sA[(r + 8) * SSTRIDE + kk + tg * 4];
                a[mt][2] = *(const uint32_t*)&sA[r * SSTRIDE + kk + 16 + tg * 4];
                a[mt][3] = *(const uint32_t*)&sA[(r + 8) * SSTRIDE + kk + 16 + tg * 4];
            }
#pragma unroll
            for (int nt = 0; nt < 8; nt++) {
                int c = wn * 64 + nt * 8 + g;
                b[nt][0] = *(const uint32_t*)&sB[c * SSTRIDE + kk + tg * 4];
                b[nt][1] = *(const uint32_t*)&sB[c * SSTRIDE + kk + 16 + tg * 4];
            }
#pragma unroll
            for (int mt = 0; mt < 2; mt++)
#pragma unroll
                for (int nt = 0; nt < 8; nt++)
                    mma_s8(acc[mt][nt], a[mt], b[nt]);
        }
        __syncthreads();
    }

    // epilogue: y = acc * (x_scale * w_scale) + bias
    const float s = (__uint_as_float(g_absmax[0]) / 127.0f) *
                    (__uint_as_float(g_absmax[1]) / 127.0f);

#pragma unroll
    for (int mt = 0; mt < 2; mt++) {
        int r0 = bm + wm * 32 + mt * 16 + g;
#pragma unroll
        for (int nt = 0; nt < 8; nt++) {
            int c0 = bn + wn * 64 + nt * 8 + tg * 2;
            float b0 = bias[c0];
            float b1 = bias[c0 + 1];
            float2 v0, v1;
            v0.x = (float)acc[mt][nt][0] * s + b0;
            v0.y = (float)acc[mt][nt][1] * s + b1;
            v1.x = (float)acc[mt][nt][2] * s + b0;
            v1.y = (float)acc[mt][nt][3] * s + b1;
            *(float2*)&out[(size_t)r0 * D_OUT + c0]       = v0;
            *(float2*)&out[(size_t)(r0 + 8) * D_OUT + c0] = v1;
        }
    }
}

// ---------------- launch ---------------------------------------------------
extern "C" void kernel_launch(void* const* d_in, const int* in_sizes, int n_in,
                              void* d_out, int out_size) {
    const float* x      = (const float*)d_in[0];
    const float* weight = (const float*)d_in[1];
    const float* bias   = (const float*)d_in[2];
    float* out          = (float*)d_out;

    const int N   = in_sizes[0] / D_IN;          // 16384
    const int n4x = in_sizes[0] / 4;             // x float4 count
    const int n4w = in_sizes[1] / 4;             // w float4 count

    int8_t* qx_ptr;  cudaGetSymbolAddress((void**)&qx_ptr, g_qx);
    int8_t* qw_ptr;  cudaGetSymbolAddress((void**)&qw_ptr, g_qw);

    init_kernel<<<1, 1>>>();
    absmax_kernel<<<1024, 256>>>(x, n4x, 0);
    absmax_kernel<<<256, 256>>>(weight, n4w, 1);
    quant_kernel<<<1024, 256>>>(x, qx_ptr, n4x, 0);
    quant_kernel<<<256, 256>>>(weight, qw_ptr, n4w, 1);

    dim3 grid(D_OUT / BN, N / BM);   // (8, 128)
    gemm_kernel<<<grid, 256>>>(bias, out, N);
}

// round 3
// speedup vs baseline: 1.1010x; 1.1010x over previous
#include <cuda_runtime.h>
#include <cstdint>

#define D_IN  1024
#define D_OUT 1024
#define MAX_N 16384

// ---------------- scratch ---------------------------------------------------
__device__ unsigned g_absmax[2];                  // [0]=x, [1]=w
__device__ int8_t   g_qx[(size_t)MAX_N * D_IN];
__device__ int8_t   g_qw[(size_t)D_OUT * D_IN];

// ---------------- base-ISA async copy helpers -------------------------------
__device__ __forceinline__ void cp16(uint32_t s, const void* g) {
    asm volatile("cp.async.cg.shared.global [%0], [%1], 16;" :: "r"(s), "l"(g));
}
#define CP_COMMIT() asm volatile("cp.async.commit_group;" ::: "memory")
#define CP_WAIT0()  asm volatile("cp.async.wait_group 0;"  ::: "memory")

__device__ __forceinline__ uint32_t smem_to_u32(const void* p) {
    uint32_t a;
    asm("{ .reg .u64 t; cvta.to.shared.u64 t, %1; cvt.u32.u64 %0, t; }" : "=r"(a) : "l"(p));
    return a;
}

__device__ __forceinline__ void ldsm_x4(uint32_t& r0, uint32_t& r1, uint32_t& r2, uint32_t& r3,
                                        uint32_t addr) {
    asm volatile("ldmatrix.sync.aligned.m8n8.x4.shared.b16 {%0,%1,%2,%3}, [%4];"
                 : "=r"(r0), "=r"(r1), "=r"(r2), "=r"(r3) : "r"(addr));
}

__device__ __forceinline__ void mma_s8(int* c, const uint32_t* a, const uint32_t* b) {
    asm volatile(
        "mma.sync.aligned.m16n8k32.row.col.s32.s8.s8.s32 "
        "{%0,%1,%2,%3}, {%4,%5,%6,%7}, {%8,%9}, {%0,%1,%2,%3};"
        : "+r"(c[0]), "+r"(c[1]), "+r"(c[2]), "+r"(c[3])
        : "r"(a[0]), "r"(a[1]), "r"(a[2]), "r"(a[3]), "r"(b[0]), "r"(b[1]));
}

// ---------------- kernel 0: reset absmax ------------------------------------
__global__ void init_kernel() { g_absmax[0] = 0u; g_absmax[1] = 0u; }

// ---------------- kernel 1: fused abs-max (x and w in one launch) -----------
__global__ void absmax_kernel(const float* __restrict__ x, const float* __restrict__ w,
                              int n4x, int n4w, int xblocks) {
    const bool isx = (int)blockIdx.x < xblocks;
    const float4* p = (const float4*)(isx ? x : w);
    const int n4   = isx ? n4x : n4w;
    const int bid  = isx ? blockIdx.x : blockIdx.x - xblocks;
    const int nblk = isx ? xblocks : (gridDim.x - xblocks);

    unsigned m = 0u;
    for (int i = bid * blockDim.x + threadIdx.x; i < n4; i += nblk * blockDim.x) {
        float4 v = p[i];
        m = max(m, __float_as_uint(fabsf(v.x)));
        m = max(m, __float_as_uint(fabsf(v.y)));
        m = max(m, __float_as_uint(fabsf(v.z)));
        m = max(m, __float_as_uint(fabsf(v.w)));
    }
    m = __reduce_max_sync(0xffffffffu, m);
    __shared__ unsigned smax[8];
    int warp = threadIdx.x >> 5, lane = threadIdx.x & 31;
    if (lane == 0) smax[warp] = m;
    __syncthreads();
    if (warp == 0) {
        m = (lane < (blockDim.x >> 5)) ? smax[lane] : 0u;
        m = __reduce_max_sync(0xffffffffu, m);
        if (lane == 0) atomicMax(&g_absmax[isx ? 0 : 1], m);
    }
}

// ---------------- kernel 2: fused quantize (x and w) ------------------------
__global__ void quant_kernel(const float* __restrict__ x, const float* __restrict__ w,
                             int8_t* __restrict__ qx, int8_t* __restrict__ qw,
                             int n4x, int n4w, int xblocks) {
    const bool isx = (int)blockIdx.x < xblocks;
    const float4* p = (const float4*)(isx ? x : w);
    int8_t* outp    = isx ? qx : qw;
    const int n4    = isx ? n4x : n4w;
    const int bid   = isx ? blockIdx.x : blockIdx.x - xblocks;
    const int nblk  = isx ? xblocks : (gridDim.x - xblocks);

    float amax = __uint_as_float(g_absmax[isx ? 0 : 1]);
    float inv  = 127.0f / amax * (amax / 127.0f) / (amax / 127.0f);  // keep exact: see below
    // exact semantics: scale = amax/127 (fp32), q = rint(v / scale). Use reciprocal:
    float scale = amax / 127.0f;
    inv = 1.0f / scale;

    uint* q = (uint*)outp;
    for (int i = bid * blockDim.x + threadIdx.x; i < n4; i += nblk * blockDim.x) {
        float4 v = p[i];
        int c0 = (int)fminf(fmaxf(rintf(v.x * inv), -127.0f), 127.0f);
        int c1 = (int)fminf(fmaxf(rintf(v.y * inv), -127.0f), 127.0f);
        int c2 = (int)fminf(fmaxf(rintf(v.z * inv), -127.0f), 127.0f);
        int c3 = (int)fminf(fmaxf(rintf(v.w * inv), -127.0f), 127.0f);
        q[i] = (uint)(c0 & 0xff) | ((uint)(c1 & 0xff) << 8) |
               ((uint)(c2 & 0xff) << 16) | ((uint)(c3 & 0xff) << 24);
    }
}

// ---------------- kernel 3: int8 GEMM (ldmatrix + mma.sync) -----------------
#define BM 128
#define BN 128
#define BK 64
#define SSTRIDE 80
#define NCHUNK (D_IN / BK)     // 16
#define STAGE_B (BM * SSTRIDE) // 10240

__global__ __launch_bounds__(256, 2)
void gemm_kernel(const float* __restrict__ bias, float* __restrict__ out) {
    __shared__ int8_t sA[2][STAGE_B];
    __shared__ int8_t sB[2][STAGE_B];

    const int tid  = threadIdx.x;
    const int warp = tid >> 5;
    const int lane = tid & 31;
    const int wm   = warp >> 1;          // 0..3
    const int wn   = warp & 1;           // 0..1
    const int g    = lane >> 2;          // 0..7
    const int tg   = lane & 3;           // 0..3

    const int bm = blockIdx.y * BM;
    const int bn = blockIdx.x * BN;

    const int8_t* gA = g_qx + (size_t)bm * D_IN;
    const int8_t* gB = g_qw + (size_t)bn * D_IN;

    // ldmatrix per-lane base offsets (within a stage buffer), before +kk
    // tiles for x4: lane>>3 selects tile, lane&7 selects row-within-tile.
    const int lrow = lane & 7;
    const int ltil = lane >> 3;          // 0..3
    // A (per mt): tile0 rows m0..m0+7 @ +0 ; tile1 rows +8 @ +0 ; tile2 rows +0 @ +16 ; tile3 rows +8 @ +16
    const int a_row_off = (ltil & 1) * 8 + lrow;
    const int a_col_off = (ltil >> 1) * 16;
    // B (per nt-pair): tile0 n0..7 @ +0 ; tile1 n0..7 @ +16 ; tile2 n8..15 @ +0 ; tile3 n8..15 @ +16
    const int b_row_off = (ltil >> 1) * 8 + lrow;
    const int b_col_off = (ltil & 1) * 16;

    const uint32_t sA0 = smem_to_u32(&sA[0][0]);
    const uint32_t sB0 = smem_to_u32(&sB[0][0]);

    int acc[2][8][4];
#pragma unroll
    for (int mt = 0; mt < 2; mt++)
#pragma unroll
        for (int nt = 0; nt < 8; nt++)
#pragma unroll
            for (int i = 0; i < 4; i++) acc[mt][nt][i] = 0;

    // stage loader: 128 rows x 64 B -> 512 x 16B, 256 threads x 2
    auto stage = [&](int c, int s) {
        const int kb = c * BK;
#pragma unroll
        for (int i = 0; i < 2; i++) {
            int idx = tid + i * 256;
            int row = idx >> 2;
            int col = (idx & 3) * 16;
            cp16(smem_to_u32(&sA[s][row * SSTRIDE + col]),
                 gA + (size_t)row * D_IN + kb + col);
            cp16(smem_to_u32(&sB[s][row * SSTRIDE + col]),
                 gB + (size_t)row * D_IN + kb + col);
        }
        CP_COMMIT();
    };

    stage(0, 0);
    CP_WAIT0();
    __syncthreads();

    for (int c = 0; c < NCHUNK; c++) {
        const int s = c & 1;
        if (c + 1 < NCHUNK) stage(c + 1, s ^ 1);

        const uint32_t aBase = sA0 + (uint32_t)s * STAGE_B;
        const uint32_t bBase = sB0 + (uint32_t)s * STAGE_B;

#pragma unroll
        for (int ks = 0; ks < 2; ks++) {
            const int kk = ks * 32;
            uint32_t a[2][4], b[8][2];
#pragma unroll
            for (int mt = 0; mt < 2; mt++) {
                uint32_t addr = aBase +
                    (uint32_t)((wm * 32 + mt * 16 + a_row_off) * SSTRIDE + kk + a_col_off);
                ldsm_x4(a[mt][0], a[mt][1], a[mt][2], a[mt][3], addr);
            }
#pragma unroll
            for (int np = 0; np < 4; np++) {        // nt pair: loads b[2np], b[2np+1]
                uint32_t addr = bBase +
                    (uint32_t)((wn * 64 + np * 16 + b_row_off) * SSTRIDE + kk + b_col_off);
                ldsm_x4(b[2 * np][0], b[2 * np][1], b[2 * np + 1][0], b[2 * np + 1][1], addr);
            }
#pragma unroll
            for (int mt = 0; mt < 2; mt++)
#pragma unroll
                for (int nt = 0; nt < 8; nt++)
                    mma_s8(acc[mt][nt], a[mt], b[nt]);
        }
        CP_WAIT0();
        __syncthreads();
    }

    // epilogue
    const float sc = (__uint_as_float(g_absmax[0]) / 127.0f) *
                     (__uint_as_float(g_absmax[1]) / 127.0f);
#pragma unroll
    for (int mt = 0; mt < 2; mt++) {
        int r0 = bm + wm * 32 + mt * 16 + g;
#pragma unroll
        for (int nt = 0; nt < 8; nt++) {
            int c0 = bn + wn * 64 + nt * 8 + tg * 2;
            float b0 = __ldg(&bias[c0]);
            float b1 = __ldg(&bias[c0 + 1]);
            float2 v0, v1;
            v0.x = (float)acc[mt][nt][0] * sc + b0;
            v0.y = (float)acc[mt][nt][1] * sc + b1;
            v1.x = (float)acc[mt][nt][2] * sc + b0;
            v1.y = (float)acc[mt][nt][3] * sc + b1;
            *(float2*)&out[(size_t)r0 * D_OUT + c0]       = v0;
            *(float2*)&out[(size_t)(r0 + 8) * D_OUT + c0] = v1;
        }
    }
}

// ---------------- launch ----------------------------------------------------
extern "C" void kernel_launch(void* const* d_in, const int* in_sizes, int n_in,
                              void* d_out, int out_size) {
    const float* x      = (const float*)d_in[0];
    const float* weight = (const float*)d_in[1];
    const float* bias   = (const float*)d_in[2];
    float* out          = (float*)d_out;

    const int N   = in_sizes[0] / D_IN;     // 16384
    const int n4x = in_sizes[0] / 4;
    const int n4w = in_sizes[1] / 4;

    int8_t* qx_ptr; cudaGetSymbolAddress((void**)&qx_ptr, g_qx);
    int8_t* qw_ptr; cudaGetSymbolAddress((void**)&qw_ptr, g_qw);

    const int XB = 2048, WB = 128;
    init_kernel<<<1, 1>>>();
    absmax_kernel<<<XB + WB, 256>>>(x, weight, n4x, n4w, XB);
    quant_kernel<<<XB + WB, 256>>>(x, weight, qx_ptr, qw_ptr, n4x, n4w, XB);

    dim3 grid(D_OUT / BN, N / BM);          // (8, 128)
    gemm_kernel<<<grid, 256>>>(bias, out);
}

// round 4
// speedup vs baseline: 1.4994x; 1.3619x over previous
#include <cuda_runtime.h>
#include <cstdint>

#define D_IN  1024
#define D_OUT 1024
#define MAX_N 16384

// ---------------- scratch ---------------------------------------------------
__device__ unsigned g_absmax[2];                  // [0]=x, [1]=w
__device__ int8_t   g_qx[(size_t)MAX_N * D_IN];
__device__ int8_t   g_qw[(size_t)D_OUT * D_IN];

// ---------------- helpers ----------------------------------------------------
__device__ __forceinline__ void cp16(uint32_t s, const void* g) {
    asm volatile("cp.async.cg.shared.global [%0], [%1], 16;" :: "r"(s), "l"(g));
}
#define CP_COMMIT() asm volatile("cp.async.commit_group;" ::: "memory")
#define CP_WAIT0()  asm volatile("cp.async.wait_group 0;"  ::: "memory")

__device__ __forceinline__ uint32_t smem_to_u32(const void* p) {
    uint32_t a;
    asm("{ .reg .u64 t; cvta.to.shared.u64 t, %1; cvt.u32.u64 %0, t; }" : "=r"(a) : "l"(p));
    return a;
}

__device__ __forceinline__ void ldsm_x4(uint32_t& r0, uint32_t& r1, uint32_t& r2, uint32_t& r3,
                                        uint32_t addr) {
    asm volatile("ldmatrix.sync.aligned.m8n8.x4.shared.b16 {%0,%1,%2,%3}, [%4];"
                 : "=r"(r0), "=r"(r1), "=r"(r2), "=r"(r3) : "r"(addr));
}

__device__ __forceinline__ void mma_s8(int* c, const uint32_t* a, const uint32_t* b) {
    asm volatile(
        "mma.sync.aligned.m16n8k32.row.col.s32.s8.s8.s32 "
        "{%0,%1,%2,%3}, {%4,%5,%6,%7}, {%8,%9}, {%0,%1,%2,%3};"
        : "+r"(c[0]), "+r"(c[1]), "+r"(c[2]), "+r"(c[3])
        : "r"(a[0]), "r"(a[1]), "r"(a[2]), "r"(a[3]), "r"(b[0]), "r"(b[1]));
}

// ---------------- kernel 0: reset absmax ------------------------------------
__global__ void init_kernel() { g_absmax[0] = 0u; g_absmax[1] = 0u; }

// ---------------- kernel 1: fused abs-max -----------------------------------
__global__ void absmax_kernel(const float* __restrict__ x, const float* __restrict__ w,
                              int n4x, int n4w, int xblocks) {
    const bool isx = (int)blockIdx.x < xblocks;
    const float4* p = (const float4*)(isx ? x : w);
    const int n4   = isx ? n4x : n4w;
    const int bid  = isx ? blockIdx.x : blockIdx.x - xblocks;
    const int nblk = isx ? xblocks : (gridDim.x - xblocks);

    unsigned m = 0u;
    for (int i = bid * blockDim.x + threadIdx.x; i < n4; i += nblk * blockDim.x) {
        float4 v = p[i];
        m = max(m, __float_as_uint(fabsf(v.x)));
        m = max(m, __float_as_uint(fabsf(v.y)));
        m = max(m, __float_as_uint(fabsf(v.z)));
        m = max(m, __float_as_uint(fabsf(v.w)));
    }
    m = __reduce_max_sync(0xffffffffu, m);
    __shared__ unsigned smax[8];
    int warp = threadIdx.x >> 5, lane = threadIdx.x & 31;
    if (lane == 0) smax[warp] = m;
    __syncthreads();
    if (warp == 0) {
        m = (lane < (blockDim.x >> 5)) ? smax[lane] : 0u;
        m = __reduce_max_sync(0xffffffffu, m);
        if (lane == 0) atomicMax(&g_absmax[isx ? 0 : 1], m);
    }
}

// ---------------- kernel 2: fused quantize ----------------------------------
__global__ void quant_kernel(const float* __restrict__ x, const float* __restrict__ w,
                             int8_t* __restrict__ qx, int8_t* __restrict__ qw,
                             int n4x, int n4w, int xblocks) {
    const bool isx = (int)blockIdx.x < xblocks;
    const float4* p = (const float4*)(isx ? x : w);
    int8_t* outp    = isx ? qx : qw;
    const int n4    = isx ? n4x : n4w;
    const int bid   = isx ? blockIdx.x : blockIdx.x - xblocks;
    const int nblk  = isx ? xblocks : (gridDim.x - xblocks);

    float amax  = __uint_as_float(g_absmax[isx ? 0 : 1]);
    float scale = amax / 127.0f;
    float inv   = 1.0f / scale;

    uint* q = (uint*)outp;
    for (int i = bid * blockDim.x + threadIdx.x; i < n4; i += nblk * blockDim.x) {
        float4 v = p[i];
        int c0 = (int)fminf(fmaxf(rintf(v.x * inv), -127.0f), 127.0f);
        int c1 = (int)fminf(fmaxf(rintf(v.y * inv), -127.0f), 127.0f);
        int c2 = (int)fminf(fmaxf(rintf(v.z * inv), -127.0f), 127.0f);
        int c3 = (int)fminf(fmaxf(rintf(v.w * inv), -127.0f), 127.0f);
        q[i] = (uint)(c0 & 0xff) | ((uint)(c1 & 0xff) << 8) |
               ((uint)(c2 & 0xff) << 16) | ((uint)(c3 & 0xff) << 24);
    }
}

// ---------------- kernel 3: hybrid tensor+dp4a int8 GEMM --------------------
// CTA 128x128. Warps 0-3 (one per SMSP): mma.sync on cols [0,64).
// Warps 4-7 (one per SMSP): dp4a on cols [64,128). Both pipes run concurrently.
#define BM 128
#define BN 128
#define BK 64
#define SSTRIDE 80
#define NCHUNK (D_IN / BK)     // 16
#define STAGE_B (BM * SSTRIDE) // 10240

__global__ __launch_bounds__(256, 2)
void gemm_kernel(const float* __restrict__ bias, float* __restrict__ out) {
    __shared__ int8_t sA[2][STAGE_B];
    __shared__ int8_t sB[2][STAGE_B];

    const int tid  = threadIdx.x;
    const int warp = tid >> 5;
    const int lane = tid & 31;

    const int bm = blockIdx.y * BM;
    const int bn = blockIdx.x * BN;

    const int8_t* gA = g_qx + (size_t)bm * D_IN;
    const int8_t* gB = g_qw + (size_t)bn * D_IN;

    const uint32_t sA0 = smem_to_u32(&sA[0][0]);
    const uint32_t sB0 = smem_to_u32(&sB[0][0]);

    // stage loader: both tiles, 128 rows x 64 B each
    auto stage = [&](int c, int s) {
        const int kb = c * BK;
#pragma unroll
        for (int i = 0; i < 2; i++) {
            int idx = tid + i * 256;
            int row = idx >> 2;
            int col = (idx & 3) * 16;
            cp16(smem_to_u32(&sA[s][row * SSTRIDE + col]), gA + (size_t)row * D_IN + kb + col);
            cp16(smem_to_u32(&sB[s][row * SSTRIDE + col]), gB + (size_t)row * D_IN + kb + col);
        }
        CP_COMMIT();
    };

    const float sc = (__uint_as_float(g_absmax[0]) / 127.0f) *
                     (__uint_as_float(g_absmax[1]) / 127.0f);

    if (warp < 4) {
        // ================= TENSOR path: rows 32*warp..+31, cols 0..63 ======
        const int wm   = warp;
        const int g    = lane >> 2;
        const int tg   = lane & 3;
        const int lrow = lane & 7;
        const int ltil = lane >> 3;
        const int a_row_off = (ltil & 1) * 8 + lrow;
        const int a_col_off = (ltil >> 1) * 16;
        const int b_row_off = (ltil >> 1) * 8 + lrow;
        const int b_col_off = (ltil & 1) * 16;

        int acc[2][8][4];
#pragma unroll
        for (int mt = 0; mt < 2; mt++)
#pragma unroll
            for (int nt = 0; nt < 8; nt++)
#pragma unroll
                for (int i = 0; i < 4; i++) acc[mt][nt][i] = 0;

        stage(0, 0);
        CP_WAIT0();
        __syncthreads();

        for (int c = 0; c < NCHUNK; c++) {
            const int s = c & 1;
            if (c + 1 < NCHUNK) stage(c + 1, s ^ 1);
            const uint32_t aBase = sA0 + (uint32_t)s * STAGE_B;
            const uint32_t bBase = sB0 + (uint32_t)s * STAGE_B;
#pragma unroll
            for (int ks = 0; ks < 2; ks++) {
                const int kk = ks * 32;
                uint32_t a[2][4], b[8][2];
#pragma unroll
                for (int mt = 0; mt < 2; mt++) {
                    uint32_t addr = aBase +
                        (uint32_t)((wm * 32 + mt * 16 + a_row_off) * SSTRIDE + kk + a_col_off);
                    ldsm_x4(a[mt][0], a[mt][1], a[mt][2], a[mt][3], addr);
                }
#pragma unroll
                for (int np = 0; np < 4; np++) {
                    uint32_t addr = bBase +
                        (uint32_t)((np * 16 + b_row_off) * SSTRIDE + kk + b_col_off);
                    ldsm_x4(b[2 * np][0], b[2 * np][1], b[2 * np + 1][0], b[2 * np + 1][1], addr);
                }
#pragma unroll
                for (int mt = 0; mt < 2; mt++)
#pragma unroll
                    for (int nt = 0; nt < 8; nt++)
                        mma_s8(acc[mt][nt], a[mt], b[nt]);
            }
            CP_WAIT0();
            __syncthreads();
        }

        // epilogue (cols bn+0..63)
#pragma unroll
        for (int mt = 0; mt < 2; mt++) {
            int r0 = bm + wm * 32 + mt * 16 + g;
#pragma unroll
            for (int nt = 0; nt < 8; nt++) {
                int c0 = bn + nt * 8 + tg * 2;
                float b0 = __ldg(&bias[c0]);
                float b1 = __ldg(&bias[c0 + 1]);
                float2 v0, v1;
                v0.x = (float)acc[mt][nt][0] * sc + b0;
                v0.y = (float)acc[mt][nt][1] * sc + b1;
                v1.x = (float)acc[mt][nt][2] * sc + b0;
                v1.y = (float)acc[mt][nt][3] * sc + b1;
                *(float2*)&out[(size_t)r0 * D_OUT + c0]       = v0;
                *(float2*)&out[(size_t)(r0 + 8) * D_OUT + c0] = v1;
            }
        }
    } else {
        // ================= DP4A path: rows 32*(warp-4)..+31, cols 64..127 ===
        const int w  = warp - 4;
        const int rb = w * 32;          // row band within tile
        const int g4 = lane >> 3;       // 0..3  (row group; rows rb+g4+4i)
        const int g8 = lane & 7;        // 0..7  (col group; cols 64+g8+8j)

        int acc[8][8];
#pragma unroll
        for (int i = 0; i < 8; i++)
#pragma unroll
            for (int j = 0; j < 8; j++) acc[i][j] = 0;

        // first stage is issued by tensor warps? No: stage() is called by ALL
        // threads (it's above the branch? it's inside each branch). Call here.
        stage(0, 0);
        CP_WAIT0();
        __syncthreads();

        for (int c = 0; c < NCHUNK; c++) {
            const int s = c & 1;
            if (c + 1 < NCHUNK) stage(c + 1, s ^ 1);

            const int8_t* aT = &sA[s][0];
            const int8_t* bT = &sB[s][0];
#pragma unroll
            for (int k8 = 0; k8 < 8; k8++) {
                const int ko = k8 * 8;
                uint2 a[8], b[8];
#pragma unroll
                for (int i = 0; i < 8; i++)
                    a[i] = *(const uint2*)&aT[(rb + g4 + 4 * i) * SSTRIDE + ko];
#pragma unroll
                for (int j = 0; j < 8; j++)
                    b[j] = *(const uint2*)&bT[(64 + g8 + 8 * j) * SSTRIDE + ko];
#pragma unroll
                for (int i = 0; i < 8; i++)
#pragma unroll
                    for (int j = 0; j < 8; j++) {
                        acc[i][j] = __dp4a((int)a[i].x, (int)b[j].x, acc[i][j]);
                        acc[i][j] = __dp4a((int)a[i].y, (int)b[j].y, acc[i][j]);
                    }
            }
            CP_WAIT0();
            __syncthreads();
        }

        // epilogue via smem restage for coalesced stores (reuse sA/sB)
        float* smf = (float*)&sA[0][0] + (size_t)w * 2048;   // 32x64 floats per warp
#pragma unroll
        for (int i = 0; i < 8; i++)
#pragma unroll
            for (int j = 0; j < 8; j++) {
                int cl = g8 + 8 * j;                         // 0..63
                smf[(g4 + 4 * i) * 64 + cl] =
                    (float)acc[i][j] * sc + __ldg(&bias[bn + 64 + cl]);
            }
        __syncwarp();
#pragma unroll
        for (int rr = 0; rr < 32; rr++) {
            float2 v = *(float2*)&smf[rr * 64 + lane * 2];
            *(float2*)&out[(size_t)(bm + rb + rr) * D_OUT + bn + 64 + lane * 2] = v;
        }
    }
}

// ---------------- launch ----------------------------------------------------
extern "C" void kernel_launch(void* const* d_in, const int* in_sizes, int n_in,
                              void* d_out, int out_size) {
    const float* x      = (const float*)d_in[0];
    const float* weight = (const float*)d_in[1];
    const float* bias   = (const float*)d_in[2];
    float* out          = (float*)d_out;

    const int N   = in_sizes[0] / D_IN;     // 16384
    const int n4x = in_sizes[0] / 4;
    const int n4w = in_sizes[1] / 4;

    int8_t* qx_ptr; cudaGetSymbolAddress((void**)&qx_ptr, g_qx);
    int8_t* qw_ptr; cudaGetSymbolAddress((void**)&qw_ptr, g_qw);

    const int XB = 2048, WB = 128;
    init_kernel<<<1, 1>>>();
    absmax_kernel<<<XB + WB, 256>>>(x, weight, n4x, n4w, XB);
    quant_kernel<<<XB + WB, 256>>>(x, weight, qx_ptr, qw_ptr, n4x, n4w, XB);

    dim3 grid(D_OUT / BN, N / BM);          // (8, 128)
    gemm_kernel<<<grid, 256>>>(bias, out);
}